// round 3
// baseline (speedup 1.0000x reference)
#include <cuda_runtime.h>

// DETRMatcher: the softmax/cdist/argmin machinery in the reference is dead code
// w.r.t. the outputs (scatter of 0 into zeros = zeros). Output is 8.1M float32:
//   [0, 1.62M)      : 0.0f           (two int32 zero tensors, 810000 each)
//   [1.62M, 4.86M)  : outputs_coord  (bitwise copy)
//   [4.86M, 8.10M)  : target_boxes   (bitwise copy)
// R2 passed with rel_err=0.0; this round: raise per-thread MLP (4 float4/thread,
// front-batched loads), int32 indexing, fewer waves.

static constexpr int V_ZERO  = 405000;                 // float4 slots of zeros
static constexpr int V_COORD = 810000;                 // float4 slots per copy
static constexpr int V_TOTAL = V_ZERO + 2 * V_COORD;   // 2,025,000

static constexpr int TPB  = 256;
static constexpr int ITER = 4;                          // float4s per thread
static constexpr int PER_BLOCK = TPB * ITER;            // 1024

__global__ void __launch_bounds__(TPB)
detr_matcher_pack_f32(const float4* __restrict__ coord,
                      const float4* __restrict__ boxes,
                      float4* __restrict__ out)
{
    const int base = blockIdx.x * PER_BLOCK + threadIdx.x;

    float4 v[ITER];
    int    idx[ITER];

    // Front-batch the loads: all LDGs issued before any STG (MLP ~4).
#pragma unroll
    for (int k = 0; k < ITER; k++) {
        const int j = base + k * TPB;
        idx[k] = j;
        float4 t = make_float4(0.f, 0.f, 0.f, 0.f);
        if (j < V_TOTAL) {
            if (j >= V_ZERO + V_COORD)      t = boxes[j - (V_ZERO + V_COORD)];
            else if (j >= V_ZERO)           t = coord[j - V_ZERO];
            // else: zero segment, keep t = 0
        }
        v[k] = t;
    }

#pragma unroll
    for (int k = 0; k < ITER; k++) {
        if (idx[k] < V_TOTAL) out[idx[k]] = v[k];
    }
}

extern "C" void kernel_launch(void* const* d_in, const int* in_sizes, int n_in,
                              void* d_out, int out_size)
{
    // metadata order: outputs_class, outputs_coord, target_classes, target_boxes
    const float4* coord = (const float4*)d_in[1];
    const float4* boxes = (const float4*)d_in[3];
    float4* out = (float4*)d_out;

    const int blocks = (V_TOTAL + PER_BLOCK - 1) / PER_BLOCK;   // 1978
    detr_matcher_pack_f32<<<blocks, TPB>>>(coord, boxes, out);
}